// round 14
// baseline (speedup 1.0000x reference)
#include <cuda_runtime.h>

// ---------------- problem constants ----------------
#define NB    384          // proposals per image
#define NC    11           // classes incl background
#define NFG   10           // foreground classes
#define NIMG  2            // images
#define NGRP  (NIMG*NFG)   // 20 NMS groups
#define MTOT  (NIMG*NB)    // 768 proposals
#define DET   100
#define MASKW 12           // ceil(384/32)
#define EPSF  1e-8f
#define SCORE_TH 0.05f
#define NMS_TH   0.5f
#define XFORM_CLIP 4.135166556742356f   // log(1000/16)
#define FULLM 0xFFFFFFFFu
#define THREADS 256

// ---------------- device scratch (no allocs allowed) ----------------
__device__ float    g_boxes [NGRP*NB*5];
__device__ unsigned long long g_gkeys[NGRP*DET];   // per-group top<=100 kept keys (sorted asc)
__device__ int      g_kcnt  [NGRP];
__device__ unsigned g_ticket = 0;   // monotonic across graph replays; each launch adds exactly NGRP

// ---------------- rotated-rect intersection: register-only, bitonic-32 network ----------------
__device__ __forceinline__ float crs(float ax,float ay,float bx,float by){
    return ax*by - ay*bx;
}

__device__ __forceinline__ float inter_area_reg(float4 ca0, float4 ca1,
                                                float4 cb0, float4 cb1)
{
    float ax[4] = {ca0.x, ca0.z, ca1.x, ca1.z};
    float ay[4] = {ca0.y, ca0.w, ca1.y, ca1.w};
    float bx4[4] = {cb0.x, cb0.z, cb1.x, cb1.z};
    float by4[4] = {cb0.y, cb0.w, cb1.y, cb1.w};
    float d1x[4],d1y[4],d2x[4],d2y[4];
    #pragma unroll
    for (int k=0;k<4;k++){
        d1x[k]=ax[(k+1)&3]-ax[k];  d1y[k]=ay[(k+1)&3]-ay[k];
        d2x[k]=bx4[(k+1)&3]-bx4[k]; d2y[k]=by4[(k+1)&3]-by4[k];
    }

    float px[24], py[24]; bool ok[24];
    #pragma unroll
    for (int i=0;i<4;i++){
        #pragma unroll
        for (int j=0;j<4;j++){
            float den  = crs(d1x[i],d1y[i],d2x[j],d2y[j]);
            float dfx  = bx4[j]-ax[i], dfy = by4[j]-ay[i];
            float dens = (fabsf(den) < EPSF) ? 1.0f : den;
            float t = crs(dfx,dfy,d2x[j],d2y[j]) / dens;
            float u = crs(dfx,dfy,d1x[i],d1y[i]) / dens;
            bool o = (fabsf(den) >= EPSF) && (t>=0.0f) && (t<=1.0f) && (u>=0.0f) && (u<=1.0f);
            px[4*i+j] = ax[i] + t*d1x[i];
            py[4*i+j] = ay[i] + t*d1y[i];
            ok[4*i+j] = o;
        }
    }
    #pragma unroll
    for (int p=0;p<4;p++){
        bool allpos=true, allneg=true;
        #pragma unroll
        for (int e=0;e<4;e++){
            float cr = crs(d2x[e],d2y[e], ax[p]-bx4[e], ay[p]-by4[e]);
            allpos = allpos && (cr >= -1e-6f);
            allneg = allneg && (cr <=  1e-6f);
        }
        ok[16+p] = allpos || allneg;
        px[16+p] = ax[p]; py[16+p] = ay[p];
    }
    #pragma unroll
    for (int p=0;p<4;p++){
        bool allpos=true, allneg=true;
        #pragma unroll
        for (int e=0;e<4;e++){
            float cr = crs(d1x[e],d1y[e], bx4[p]-ax[e], by4[p]-ay[e]);
            allpos = allpos && (cr >= -1e-6f);
            allneg = allneg && (cr <=  1e-6f);
        }
        ok[20+p] = allpos || allneg;
        px[20+p] = bx4[p]; py[20+p] = by4[p];
    }

    int nv = 0; float cx = 0.0f, cy = 0.0f;
    #pragma unroll
    for (int i=0;i<24;i++) if (ok[i]){ nv++; cx += px[i]; cy += py[i]; }
    if (nv < 3) return 0.0f;
    cx /= (float)nv;  cy /= (float)nv;

    // reference semantics: 24 points, invalid parked AT centroid with angle +0,
    // sorted by angle, shoelace over cyclic order. Ties occur only among
    // coordinate-identical centroid copies -> any order gives the same sum.
    unsigned kk[32];
    float sxp[32], syp[32];
    #pragma unroll
    for (int i=0;i<24;i++){
        bool o = ok[i];
        float x = o ? px[i] : cx;
        float y = o ? py[i] : cy;
        float a = o ? atan2f(y-cy, x-cx) : 0.0f;
        unsigned u = __float_as_uint(a);
        u = (u & 0x80000000u) ? ~u : (u | 0x80000000u);
        kk[i] = u; sxp[i] = x; syp[i] = y;
    }
    #pragma unroll
    for (int i=24;i<32;i++){ kk[i] = 0xFFFFFFFFu; sxp[i] = cx; syp[i] = cy; }

    #pragma unroll
    for (int k=2;k<=32;k<<=1){
        #pragma unroll
        for (int j=k>>1;j>0;j>>=1){
            #pragma unroll
            for (int ii=0;ii<32;ii++){
                int jj = ii ^ j;
                if (jj > ii){
                    bool up = ((ii & k) == 0);
                    bool sw = (kk[ii] > kk[jj]) == up;
                    unsigned ka=kk[ii], kb=kk[jj];
                    float xa=sxp[ii], xb=sxp[jj];
                    float ya=syp[ii], yb=syp[jj];
                    kk[ii]=sw?kb:ka;  kk[jj]=sw?ka:kb;
                    sxp[ii]=sw?xb:xa; sxp[jj]=sw?xa:xb;
                    syp[ii]=sw?yb:ya; syp[jj]=sw?ya:yb;
                }
            }
        }
    }
    float s = 0.0f;
    #pragma unroll
    for (int i=0;i<24;i++){
        int jn = (i+1) % 24;
        s += sxp[i]*syp[jn] - syp[i]*sxp[jn];
    }
    return 0.5f*fabsf(s);
}

// ---------------- the single kernel: one block per NMS group ----------------
__global__ void __launch_bounds__(THREADS, 1)
k_all(const float* __restrict__ logits,
      const float* __restrict__ reg,
      const float* __restrict__ rr,
      float* __restrict__ out, int out_size)
{
    __shared__ __align__(16) unsigned long long skeys[512];  // 4KB; aliased as warp queues later
    __shared__ __align__(16) float  scorn[NB*8];             // 12KB; aliased as topk sk later
    __shared__ __align__(16) float4 smeta[NB];               // 6KB;  aliased as topk stage later
    __shared__ float    spsc [NB];
    __shared__ int      svlist[NB];
    __shared__ unsigned smask[NB*MASKW];                     // 18KB
    __shared__ unsigned sblk[MASKW];
    __shared__ int      soff[NFG+1];
    __shared__ int      samLast;

    int g = blockIdx.x;
    int t = threadIdx.x;
    int bimg = g / NFG, cf = g % NFG, c = cf + 1;
    int lane = t & 31, warp = t >> 5;

    // ================= phase 1: decode + softmax + corners =================
    bool val0 = false, val1 = false;
    #pragma unroll
    for (int rep = 0; rep < 2; rep++){
        int idx = t + rep*THREADS;
        if (idx < NB){
            int m = bimg*NB + idx;
            float mx = -1e30f;
            float l[NC];
            #pragma unroll
            for (int k=0;k<NC;k++){ l[k] = __ldg(&logits[m*NC+k]); mx = fmaxf(mx, l[k]); }
            float s = 0.f;
            #pragma unroll
            for (int k=0;k<NC;k++) s += expf(l[k]-mx);
            float prob = expf(l[c]-mx)/s;

            float xc = __ldg(&rr[m*5+0]), yc = __ldg(&rr[m*5+1]);
            float w  = __ldg(&rr[m*5+2]), h  = __ldg(&rr[m*5+3]), a = __ldg(&rr[m*5+4]);

            const float* r = &reg[m*(NC*5) + c*5];
            float dx = __ldg(&r[0])/10.0f;
            float dy = __ldg(&r[1])/10.0f;
            float dw = fminf(__ldg(&r[2])/5.0f, XFORM_CLIP);
            float dh = fminf(__ldg(&r[3])/5.0f, XFORM_CLIP);
            float da = __ldg(&r[4]);

            float pxc = dx*w + xc;
            float pyc = dy*h + yc;
            float pw  = expf(dw)*w;
            float ph  = expf(dh)*h;
            float pa  = da*(float)(180.0/3.14159265358979323846) + a;
            float x2 = pa + 180.0f;
            float rm = fmodf(x2, 360.0f);
            if (rm < 0.0f) rm += 360.0f;
            pa = rm - 180.0f;

            int o = g*NB + idx;
            g_boxes[o*5+0] = pxc; g_boxes[o*5+1] = pyc;
            g_boxes[o*5+2] = pw;  g_boxes[o*5+3] = ph; g_boxes[o*5+4] = pa;

            smeta[idx] = make_float4(pxc, pyc, pw*ph, 0.5f*sqrtf(pw*pw + ph*ph));

            float th = pa*(float)(3.14159265358979323846/180.0);
            float cs = cosf(th), sn = sinf(th);
            float hx = pw*0.5f, hy = ph*0.5f;
            float lx[4] = {-hx, hx, hx, -hx};
            float ly[4] = {-hy, -hy, hy, hy};
            #pragma unroll
            for (int k=0;k<4;k++){
                scorn[idx*8+2*k]   = pxc + lx[k]*cs - ly[k]*sn;
                scorn[idx*8+2*k+1] = pyc + lx[k]*sn + ly[k]*cs;
            }

            bool v = prob > SCORE_TH;
            if (rep == 0) val0 = v; else val1 = v;
            float kf = v ? prob : __int_as_float(0xFF800000);
            unsigned ub = __float_as_uint(kf);
            ub = (ub & 0x80000000u) ? ~ub : (ub | 0x80000000u);
            skeys[idx] = (((unsigned long long)(~ub)) << 32) | (unsigned)idx;
        } else {
            skeys[idx] = 0xFFFFFFFF00000000ull | (unsigned)idx;
        }
    }
    // zero suppression mask while we're here
    for (int w2 = t; w2 < NB*MASKW; w2 += THREADS) smask[w2] = 0u;
    if (t < MASKW) sblk[t] = 0u;
    int vv = __syncthreads_count(val0) + __syncthreads_count(val1);

    // ================= phase 2: bitonic-512 sort (2 elems/thread) =================
    for (int k=2;k<=512;k<<=1)
        for (int j=k>>1;j>0;j>>=1){
            __syncthreads();
            #pragma unroll
            for (int rep=0; rep<2; rep++){
                int p = t + rep*THREADS;
                int ixj = p ^ j;
                if (ixj > p){
                    unsigned long long A = skeys[p], Bv = skeys[ixj];
                    if ((A > Bv) == ((p & k) == 0)){ skeys[p] = Bv; skeys[ixj] = A; }
                }
            }
        }
    __syncthreads();

    // ================= phase 3: in-place permute to sorted order =================
    {
        float4 m0, m1; float c0[8], c1[8]; float s0=0.f, s1=0.f; int n0=-1, n1=-1;
        if (t < vv){
            unsigned long long key = skeys[t];
            n0 = (int)(key & 0xFFFFFFFFull);
            unsigned ub = ~(unsigned)(key >> 32);
            unsigned bits = (ub & 0x80000000u) ? (ub ^ 0x80000000u) : ~ub;
            s0 = __uint_as_float(bits);
            m0 = smeta[n0];
            #pragma unroll
            for (int k=0;k<8;k++) c0[k] = scorn[n0*8+k];
        }
        int t1 = t + THREADS;
        if (t1 < vv){
            unsigned long long key = skeys[t1];
            n1 = (int)(key & 0xFFFFFFFFull);
            unsigned ub = ~(unsigned)(key >> 32);
            unsigned bits = (ub & 0x80000000u) ? (ub ^ 0x80000000u) : ~ub;
            s1 = __uint_as_float(bits);
            m1 = smeta[n1];
            #pragma unroll
            for (int k=0;k<8;k++) c1[k] = scorn[n1*8+k];
        }
        __syncthreads();
        if (n0 >= 0){
            svlist[t] = n0; spsc[t] = s0; smeta[t] = m0;
            #pragma unroll
            for (int k=0;k<8;k++) scorn[t*8+k] = c0[k];
        }
        if (n1 >= 0){
            svlist[t1] = n1; spsc[t1] = s1; smeta[t1] = m1;
            #pragma unroll
            for (int k=0;k<8;k++) scorn[t1*8+k] = c1[k];
        }
    }
    __syncthreads();

    // ================= phase 4: pairs — warp-private queues, lockstep clips =================
    {
        unsigned* wq = ((unsigned*)skeys) + warp*64;   // skeys no longer needed
        const float4* cor4 = (const float4*)scorn;
        int qn = 0;
        int P = vv*(vv-1)/2;
        for (int p0 = warp*32; p0 < P; p0 += THREADS){
            int p = p0 + lane;
            bool sv = false;
            unsigned pk = 0;
            if (p < P){
                int j = (int)((1.0f + sqrtf(1.0f + 8.0f*(float)p))*0.5f);
                while (j*(j-1)/2 > p) j--;
                while ((j+1)*j/2 <= p) j++;
                int i = p - j*(j-1)/2;
                float4 mi = smeta[i];
                float4 mj = smeta[j];
                float aA = mi.z, aB = mj.z;
                float mn = fminf(aA,aB), smv = aA + aB;
                if (3.0f*mn > smv*(1.0f - 1e-4f)){
                    float dx = mi.x-mj.x, dy = mi.y-mj.y;
                    float rr2 = mi.w+mj.w;
                    if (dx*dx + dy*dy < rr2*rr2){ sv = true; pk = ((unsigned)i<<9) | (unsigned)j; }
                }
            }
            unsigned bal = __ballot_sync(FULLM, sv);
            int pos = qn + __popc(bal & ((1u<<lane)-1u));
            if (sv) wq[pos] = pk;
            qn += __popc(bal);
            if (qn >= 32){
                qn -= 32;
                unsigned item = wq[qn + lane];
                int i = item >> 9, j = item & 511;
                float inter = inter_area_reg(cor4[i*2], cor4[i*2+1], cor4[j*2], cor4[j*2+1]);
                float aA = smeta[i].z, aB = smeta[j].z;
                float iou = inter / (aA + aB - inter + EPSF);
                if (iou > NMS_TH)
                    atomicOr(&smask[i*MASKW + (j>>5)], 1u << (j&31));
            }
        }
        if (lane < qn){                       // drain tail (divergent, <=31 clips)
            unsigned item = wq[lane];
            int i = item >> 9, j = item & 511;
            float inter = inter_area_reg(cor4[i*2], cor4[i*2+1], cor4[j*2], cor4[j*2+1]);
            float aA = smeta[i].z, aB = smeta[j].z;
            float iou = inter / (aA + aB - inter + EPSF);
            if (iou > NMS_TH)
                atomicOr(&smask[i*MASKW + (j>>5)], 1u << (j&31));
        }
    }
    __syncthreads();

    // ================= phase 5: greedy + per-group top<=100 key emission =================
    {
        int v = vv;
        int B = (v + 31) & ~31;
        for (int r0 = t; r0 < B; r0 += THREADS){
            bool any = false;
            if (r0 < v){
                unsigned o = 0u;
                #pragma unroll
                for (int w2=0;w2<MASKW;w2++) o |= smask[r0*MASKW+w2];
                any = (o != 0u);
            }
            unsigned bal = __ballot_sync(FULLM, any);
            if ((t & 31) == 0) sblk[r0 >> 5] = bal;
        }
        __syncthreads();

        if (t < 32){
            unsigned sup = 0u;                   // lane b owns sup word b
            int nblk = (v + 31) >> 5;
            for (int b=0; b<nblk; b++){
                unsigned sb = sblk[b];
                if (sb == 0u) continue;
                unsigned s = __shfl_sync(FULLM, sup, b);
                if (lane == 0){
                    unsigned it = sb;
                    while (it){
                        int l = __ffs(it) - 1; it &= it - 1u;
                        if (!((s >> l) & 1u)) s |= smask[(b*32+l)*MASKW + b];
                    }
                }
                s = __shfl_sync(FULLM, s, 0);
                unsigned kept = (~s) & sb;
                if (lane < MASKW){
                    unsigned acc = 0u, it = kept;
                    while (it){
                        int l = __ffs(it) - 1; it &= it - 1u;
                        acc |= smask[(b*32+l)*MASKW + lane];
                    }
                    sup |= acc;
                }
            }
            int ofs = 0;
            for (int bb=0; bb<v; bb+=32){
                int tp = bb + lane;
                int src = (tp < v) ? (tp>>5) : 0;
                unsigned wv = __shfl_sync(FULLM, sup, src);
                bool kp = (tp < v) && !((wv >> (tp&31)) & 1u);
                unsigned bal = __ballot_sync(FULLM, kp);
                int pos = ofs + __popc(bal & ((1u<<lane)-1u));
                if (kp && pos < DET){
                    int n = svlist[tp];
                    unsigned kh = ~(__float_as_uint(spsc[tp]) | 0x80000000u);
                    unsigned fidx = (unsigned)(cf*NB + n);
                    g_gkeys[g*DET+pos] = (((unsigned long long)kh) << 32) | fidx;
                }
                ofs += __popc(bal);
                if (ofs >= DET) break;
            }
            if (lane == 0) g_kcnt[g] = ofs < DET ? ofs : DET;
        }
    }
    __threadfence();
    __syncthreads();

    // ================= phase 6: ticket — last block runs top-k inline =================
    if (t == 0){
        unsigned old = atomicAdd(&g_ticket, 1u);     // monotonic: each launch adds exactly NGRP
        samLast = ((old % NGRP) == NGRP-1);
    }
    __syncthreads();
    if (!samLast) return;

    unsigned long long* sk    = (unsigned long long*)scorn;   // 8000B <= 12288B
    unsigned long long* stage = (unsigned long long*)smeta;   // 800B  <= 6144B

    for (int b = 0; b < NIMG; b++){
        if (t == 0){
            int acc = 0;
            #pragma unroll
            for (int i=0;i<NFG;i++){ soff[i] = acc; acc += g_kcnt[b*NFG+i]; }
            soff[NFG] = acc;
        }
        if (t < DET) stage[t] = 0xFFFFFFFFFFFFFFFFull;   // real keys have MSB=0
        __syncthreads();
        int M = soff[NFG];
        int need = M < DET ? M : DET;

        #pragma unroll
        for (int gi=0; gi<NFG; gi++){
            int off = soff[gi];
            int cnt = soff[gi+1] - off;
            for (int p=t; p<cnt; p+=THREADS) sk[off+p] = g_gkeys[(b*NFG+gi)*DET + p];
        }
        __syncthreads();

        // exact global rank: rank = local_idx + sum of lower_bounds in other lists
        for (int cpos = t; cpos < M; cpos += THREADS){
            int gi = 0;
            #pragma unroll
            for (int q=1;q<NFG;q++) gi += (soff[q] <= cpos);
            int j = cpos - soff[gi];
            if (j >= need) continue;
            unsigned long long k = sk[cpos];
            int rank = j;
            #pragma unroll 1
            for (int og = 0; og < NFG; og++){
                if (og == gi) continue;
                int lo = soff[og], hi = soff[og+1];
                while (lo < hi){
                    int mid = (lo + hi) >> 1;
                    if (sk[mid] < k) lo = mid + 1; else hi = mid;
                }
                rank += lo - soff[og];
                if (rank >= need) break;
            }
            if (rank < need) stage[rank] = k;    // ranks unique (keys unique)
        }
        __syncthreads();

        if (t < DET){
            unsigned long long key = stage[t];
            bool okd = (key != 0xFFFFFFFFFFFFFFFFull);
            float vals[6] = {0.f,0.f,0.f,0.f,0.f,0.f};
            float lab = 0.0f;
            if (okd){
                unsigned f  = (unsigned)(key & 0xFFFFFFFFull);
                unsigned ub = ~((unsigned)(key >> 32));
                float sc = __uint_as_float(ub ^ 0x80000000u);   // kept scores > 0
                int bi = b*NFG*NB + (int)f;
                #pragma unroll
                for (int kk2=0;kk2<5;kk2++) vals[kk2] = g_boxes[bi*5+kk2];
                vals[5] = sc;
                lab = (float)((int)f / NB + 1);
            }
            int obase = b*DET*6 + t*6;
            #pragma unroll
            for (int kk2=0;kk2<6;kk2++) if (obase+kk2 < out_size) out[obase+kk2] = vals[kk2];
            int li = NIMG*DET*6 + b*DET + t;
            if (li < out_size) out[li] = lab;
        }
        __syncthreads();
    }
}

// ---------------- launcher ----------------
extern "C" void kernel_launch(void* const* d_in, const int* in_sizes, int n_in,
                              void* d_out, int out_size)
{
    const float* logits = (const float*)d_in[0];   // (768, 11)
    const float* reg    = (const float*)d_in[1];   // (768, 55)
    const float* rr     = (const float*)d_in[2];   // (768, 5)

    k_all<<<NGRP, THREADS>>>(logits, reg, rr, (float*)d_out, out_size);
}

// round 15
// speedup vs baseline: 1.2220x; 1.2220x over previous
#include <cuda_runtime.h>

// ---------------- problem constants ----------------
#define NB    384          // proposals per image
#define NC    11           // classes incl background
#define NFG   10           // foreground classes
#define NIMG  2            // images
#define NGRP  (NIMG*NFG)   // 20 NMS groups
#define MTOT  (NIMG*NB)    // 768 proposals
#define DET   100
#define MASKW 12           // ceil(384/32)
#define EPSF  1e-8f
#define SCORE_TH 0.05f
#define NMS_TH   0.5f
#define XFORM_CLIP 4.135166556742356f   // log(1000/16)
#define FULLM 0xFFFFFFFFu
#define THREADS 256

// ---------------- device scratch (no allocs allowed) ----------------
__device__ float    g_boxes [NGRP*NB*5];
__device__ int      g_vcnt  [NGRP];
__device__ int      g_vlist [NGRP*NB];
__device__ float    g_psc   [NGRP*NB];
__device__ unsigned g_mask  [NGRP*NB*MASKW];
__device__ unsigned long long g_gkeys[NGRP*DET];   // per-group top<=100 kept keys (sorted asc)
__device__ int      g_kcnt  [NGRP];

// ---------------- rotated-rect intersection: register-only, bitonic-32 network ----------------
__device__ __forceinline__ float crs(float ax,float ay,float bx,float by){
    return ax*by - ay*bx;
}

__device__ __forceinline__ float inter_area_reg(float4 ca0, float4 ca1,
                                                float4 cb0, float4 cb1)
{
    float ax[4] = {ca0.x, ca0.z, ca1.x, ca1.z};
    float ay[4] = {ca0.y, ca0.w, ca1.y, ca1.w};
    float bx4[4] = {cb0.x, cb0.z, cb1.x, cb1.z};
    float by4[4] = {cb0.y, cb0.w, cb1.y, cb1.w};
    float d1x[4],d1y[4],d2x[4],d2y[4];
    #pragma unroll
    for (int k=0;k<4;k++){
        d1x[k]=ax[(k+1)&3]-ax[k];  d1y[k]=ay[(k+1)&3]-ay[k];
        d2x[k]=bx4[(k+1)&3]-bx4[k]; d2y[k]=by4[(k+1)&3]-by4[k];
    }

    float px[24], py[24]; bool ok[24];
    #pragma unroll
    for (int i=0;i<4;i++){
        #pragma unroll
        for (int j=0;j<4;j++){
            float den  = crs(d1x[i],d1y[i],d2x[j],d2y[j]);
            float dfx  = bx4[j]-ax[i], dfy = by4[j]-ay[i];
            float dens = (fabsf(den) < EPSF) ? 1.0f : den;
            float t = crs(dfx,dfy,d2x[j],d2y[j]) / dens;
            float u = crs(dfx,dfy,d1x[i],d1y[i]) / dens;
            bool o = (fabsf(den) >= EPSF) && (t>=0.0f) && (t<=1.0f) && (u>=0.0f) && (u<=1.0f);
            px[4*i+j] = ax[i] + t*d1x[i];
            py[4*i+j] = ay[i] + t*d1y[i];
            ok[4*i+j] = o;
        }
    }
    #pragma unroll
    for (int p=0;p<4;p++){
        bool allpos=true, allneg=true;
        #pragma unroll
        for (int e=0;e<4;e++){
            float cr = crs(d2x[e],d2y[e], ax[p]-bx4[e], ay[p]-by4[e]);
            allpos = allpos && (cr >= -1e-6f);
            allneg = allneg && (cr <=  1e-6f);
        }
        ok[16+p] = allpos || allneg;
        px[16+p] = ax[p]; py[16+p] = ay[p];
    }
    #pragma unroll
    for (int p=0;p<4;p++){
        bool allpos=true, allneg=true;
        #pragma unroll
        for (int e=0;e<4;e++){
            float cr = crs(d1x[e],d1y[e], bx4[p]-ax[e], by4[p]-ay[e]);
            allpos = allpos && (cr >= -1e-6f);
            allneg = allneg && (cr <=  1e-6f);
        }
        ok[20+p] = allpos || allneg;
        px[20+p] = bx4[p]; py[20+p] = by4[p];
    }

    int nv = 0; float cx = 0.0f, cy = 0.0f;
    #pragma unroll
    for (int i=0;i<24;i++) if (ok[i]){ nv++; cx += px[i]; cy += py[i]; }
    if (nv < 3) return 0.0f;
    cx /= (float)nv;  cy /= (float)nv;

    // reference semantics: 24 points, invalid parked AT centroid with angle +0,
    // sorted by angle, shoelace over cyclic order. Ties occur only among
    // coordinate-identical centroid copies -> any order gives the same sum.
    unsigned kk[32];
    float sxp[32], syp[32];
    #pragma unroll
    for (int i=0;i<24;i++){
        bool o = ok[i];
        float x = o ? px[i] : cx;
        float y = o ? py[i] : cy;
        float a = o ? atan2f(y-cy, x-cx) : 0.0f;
        unsigned u = __float_as_uint(a);
        u = (u & 0x80000000u) ? ~u : (u | 0x80000000u);
        kk[i] = u; sxp[i] = x; syp[i] = y;
    }
    #pragma unroll
    for (int i=24;i<32;i++){ kk[i] = 0xFFFFFFFFu; sxp[i] = cx; syp[i] = cy; }

    #pragma unroll
    for (int k=2;k<=32;k<<=1){
        #pragma unroll
        for (int j=k>>1;j>0;j>>=1){
            #pragma unroll
            for (int ii=0;ii<32;ii++){
                int jj = ii ^ j;
                if (jj > ii){
                    bool up = ((ii & k) == 0);
                    bool sw = (kk[ii] > kk[jj]) == up;
                    unsigned ka=kk[ii], kb=kk[jj];
                    float xa=sxp[ii], xb=sxp[jj];
                    float ya=syp[ii], yb=syp[jj];
                    kk[ii]=sw?kb:ka;  kk[jj]=sw?ka:kb;
                    sxp[ii]=sw?xb:xa; sxp[jj]=sw?xa:xb;
                    syp[ii]=sw?yb:ya; syp[jj]=sw?ya:yb;
                }
            }
        }
    }
    float s = 0.0f;
    #pragma unroll
    for (int i=0;i<24;i++){
        int jn = (i+1) % 24;
        s += sxp[i]*syp[jn] - syp[i]*sxp[jn];
    }
    return 0.5f*fabsf(s);
}

// ---------------- kernel 1: fused decode+sort (redundant per block) + pairs ----------------
// grid = NGRP * MASKW. Block (g, w) owns all pairs whose j lies in word w
// -> mask word (i, w) written by exactly ONE block: plain stores, no zeroing kernel.
__global__ void __launch_bounds__(THREADS, 1)
k_decpairs(const float* __restrict__ logits,
           const float* __restrict__ reg,
           const float* __restrict__ rr)
{
    __shared__ __align__(16) unsigned long long skeys[512];   // sort keys; aliased as warp queues
    __shared__ __align__(16) float  scorn[NB*8];               // corners (sorted order)
    __shared__ __align__(16) float4 smeta[NB];                 // (cx,cy,area,rad) (sorted order)
    __shared__ unsigned ssup[NB];                              // this block's mask word per row i

    int g = blockIdx.x / MASKW;
    int w = blockIdx.x % MASKW;
    int t = threadIdx.x;
    int bimg = g / NFG, cf = g % NFG, c = cf + 1;
    int lane = t & 31, warp = t >> 5;

    // ---- decode + softmax + corners (every block, redundantly) ----
    bool val0 = false, val1 = false;
    #pragma unroll
    for (int rep = 0; rep < 2; rep++){
        int idx = t + rep*THREADS;
        if (idx < NB){
            int m = bimg*NB + idx;
            float mx = -1e30f;
            float l[NC];
            #pragma unroll
            for (int k=0;k<NC;k++){ l[k] = __ldg(&logits[m*NC+k]); mx = fmaxf(mx, l[k]); }
            float s = 0.f;
            #pragma unroll
            for (int k=0;k<NC;k++) s += expf(l[k]-mx);
            float prob = expf(l[c]-mx)/s;

            float xc = __ldg(&rr[m*5+0]), yc = __ldg(&rr[m*5+1]);
            float wd = __ldg(&rr[m*5+2]), h  = __ldg(&rr[m*5+3]), a = __ldg(&rr[m*5+4]);

            const float* r = &reg[m*(NC*5) + c*5];
            float dx = __ldg(&r[0])/10.0f;
            float dy = __ldg(&r[1])/10.0f;
            float dw = fminf(__ldg(&r[2])/5.0f, XFORM_CLIP);
            float dh = fminf(__ldg(&r[3])/5.0f, XFORM_CLIP);
            float da = __ldg(&r[4]);

            float pxc = dx*wd + xc;
            float pyc = dy*h  + yc;
            float pw  = expf(dw)*wd;
            float ph  = expf(dh)*h;
            float pa  = da*(float)(180.0/3.14159265358979323846) + a;
            float x2 = pa + 180.0f;
            float rm = fmodf(x2, 360.0f);
            if (rm < 0.0f) rm += 360.0f;
            pa = rm - 180.0f;

            if (w == 0){
                int o = g*NB + idx;
                g_boxes[o*5+0] = pxc; g_boxes[o*5+1] = pyc;
                g_boxes[o*5+2] = pw;  g_boxes[o*5+3] = ph; g_boxes[o*5+4] = pa;
            }

            smeta[idx] = make_float4(pxc, pyc, pw*ph, 0.5f*sqrtf(pw*pw + ph*ph));

            float th = pa*(float)(3.14159265358979323846/180.0);
            float cs = cosf(th), sn = sinf(th);
            float hx = pw*0.5f, hy = ph*0.5f;
            float lx[4] = {-hx, hx, hx, -hx};
            float ly[4] = {-hy, -hy, hy, hy};
            #pragma unroll
            for (int k=0;k<4;k++){
                scorn[idx*8+2*k]   = pxc + lx[k]*cs - ly[k]*sn;
                scorn[idx*8+2*k+1] = pyc + lx[k]*sn + ly[k]*cs;
            }

            bool v = prob > SCORE_TH;
            if (rep == 0) val0 = v; else val1 = v;
            float kf = v ? prob : __int_as_float(0xFF800000);
            unsigned ub = __float_as_uint(kf);
            ub = (ub & 0x80000000u) ? ~ub : (ub | 0x80000000u);
            skeys[idx] = (((unsigned long long)(~ub)) << 32) | (unsigned)idx;
        } else {
            skeys[idx] = 0xFFFFFFFF00000000ull | (unsigned)idx;
        }
    }
    for (int i2 = t; i2 < NB; i2 += THREADS) ssup[i2] = 0u;
    int vv = __syncthreads_count(val0) + __syncthreads_count(val1);
    if (t == 0 && w == 0) g_vcnt[g] = vv;

    // ---- bitonic-512 sort (2 elems/thread) ----
    for (int k=2;k<=512;k<<=1)
        for (int j=k>>1;j>0;j>>=1){
            __syncthreads();
            #pragma unroll
            for (int rep=0; rep<2; rep++){
                int p = t + rep*THREADS;
                int ixj = p ^ j;
                if (ixj > p){
                    unsigned long long A = skeys[p], Bv = skeys[ixj];
                    if ((A > Bv) == ((p & k) == 0)){ skeys[p] = Bv; skeys[ixj] = A; }
                }
            }
        }
    __syncthreads();

    // ---- in-place permute to sorted order (+ w==0 publishes vlist/psc) ----
    {
        float4 m0, m1; float c0[8], c1[8]; int n0=-1, n1=-1;
        if (t < vv){
            unsigned long long key = skeys[t];
            n0 = (int)(key & 0xFFFFFFFFull);
            m0 = smeta[n0];
            #pragma unroll
            for (int k=0;k<8;k++) c0[k] = scorn[n0*8+k];
            if (w == 0){
                unsigned ub = ~(unsigned)(key >> 32);
                unsigned bits = (ub & 0x80000000u) ? (ub ^ 0x80000000u) : ~ub;
                g_vlist[g*NB+t] = n0;
                g_psc [g*NB+t] = __uint_as_float(bits);
            }
        }
        int t1 = t + THREADS;
        if (t1 < vv){
            unsigned long long key = skeys[t1];
            n1 = (int)(key & 0xFFFFFFFFull);
            m1 = smeta[n1];
            #pragma unroll
            for (int k=0;k<8;k++) c1[k] = scorn[n1*8+k];
            if (w == 0){
                unsigned ub = ~(unsigned)(key >> 32);
                unsigned bits = (ub & 0x80000000u) ? (ub ^ 0x80000000u) : ~ub;
                g_vlist[g*NB+t1] = n1;
                g_psc [g*NB+t1] = __uint_as_float(bits);
            }
        }
        __syncthreads();
        if (n0 >= 0){
            smeta[t] = m0;
            #pragma unroll
            for (int k=0;k<8;k++) scorn[t*8+k] = c0[k];
        }
        if (n1 >= 0){
            smeta[t1] = m1;
            #pragma unroll
            for (int k=0;k<8;k++) scorn[t1*8+k] = c1[k];
        }
    }
    __syncthreads();

    // ---- pairs for j in word w: prefilter -> warp queue -> lockstep clips ----
    {
        unsigned* wq = ((unsigned*)skeys) + warp*64;   // skeys no longer needed
        const float4* cor4 = (const float4*)scorn;
        int qn = 0;
        int jhi = 32*w + 32 < vv ? 32*w + 32 : vv;
        for (int j = 32*w; j < jhi; j++){
            float4 mj = smeta[j];
            for (int i0 = 0; i0 < j; i0 += THREADS){
                int i = i0 + t;
                bool sv = false;
                unsigned pk = 0;
                if (i < j){
                    float4 mi = smeta[i];
                    float aA = mi.z, aB = mj.z;
                    float mn = fminf(aA,aB), smv = aA + aB;
                    if (3.0f*mn > smv*(1.0f - 1e-4f)){
                        float dx = mi.x-mj.x, dy = mi.y-mj.y;
                        float rr2 = mi.w+mj.w;
                        if (dx*dx + dy*dy < rr2*rr2){ sv = true; pk = ((unsigned)i<<5) | (unsigned)(j & 31); }
                    }
                }
                unsigned bal = __ballot_sync(FULLM, sv);
                int pos = qn + __popc(bal & ((1u<<lane)-1u));
                if (sv) wq[pos] = pk;
                qn += __popc(bal);
                if (qn >= 32){
                    qn -= 32;
                    unsigned item = wq[qn + lane];
                    int ii = item >> 5, jj = (int)(item & 31u) + 32*w;
                    float inter = inter_area_reg(cor4[ii*2], cor4[ii*2+1], cor4[jj*2], cor4[jj*2+1]);
                    float aA = smeta[ii].z, aB = smeta[jj].z;
                    float iou = inter / (aA + aB - inter + EPSF);
                    if (iou > NMS_TH)
                        atomicOr(&ssup[ii], 1u << (jj & 31));
                }
            }
        }
        if (lane < qn){                       // drain tail
            unsigned item = wq[lane];
            int ii = item >> 5, jj = (int)(item & 31u) + 32*w;
            float inter = inter_area_reg(cor4[ii*2], cor4[ii*2+1], cor4[jj*2], cor4[jj*2+1]);
            float aA = smeta[ii].z, aB = smeta[jj].z;
            float iou = inter / (aA + aB - inter + EPSF);
            if (iou > NMS_TH)
                atomicOr(&ssup[ii], 1u << (jj & 31));
        }
    }
    __syncthreads();

    // ---- write this block's exclusively-owned mask words (no zeroing needed) ----
    for (int i2 = t; i2 < vv; i2 += THREADS)
        g_mask[(g*NB+i2)*MASKW + w] = ssup[i2];
}

// ---------------- kernel 2: greedy + per-group top<=100 kept-key emission ----------------
__global__ void __launch_bounds__(256) k_greedy()
{
    __shared__ unsigned sm[NB*MASKW];
    __shared__ unsigned sblk[MASKW];
    int g = blockIdx.x;
    int t = threadIdx.x;
    int v = g_vcnt[g];
    int cf = g % NFG;
    int lane = t & 31;

    for (int w = t; w < v*MASKW; w += 256) sm[w] = g_mask[g*NB*MASKW + w];
    if (t < MASKW) sblk[t] = 0u;
    __syncthreads();

    int B = (v + 31) & ~31;
    for (int r0 = t; r0 < B; r0 += 256){
        bool any = false;
        if (r0 < v){
            unsigned o = 0u;
            #pragma unroll
            for (int w2=0;w2<MASKW;w2++) o |= sm[r0*MASKW+w2];
            any = (o != 0u);
        }
        unsigned bal = __ballot_sync(FULLM, any);
        if ((t & 31) == 0) sblk[r0 >> 5] = bal;
    }
    __syncthreads();

    if (t < 32){
        unsigned sup = 0u;                       // lane b owns sup word b
        int nblk = (v + 31) >> 5;
        for (int b=0; b<nblk; b++){
            unsigned sb = sblk[b];
            if (sb == 0u) continue;
            unsigned s = __shfl_sync(FULLM, sup, b);
            if (lane == 0){
                unsigned it = sb;
                while (it){
                    int l = __ffs(it) - 1; it &= it - 1u;
                    if (!((s >> l) & 1u)) s |= sm[(b*32+l)*MASKW + b];
                }
            }
            s = __shfl_sync(FULLM, s, 0);
            unsigned kept = (~s) & sb;
            if (lane < MASKW){
                unsigned acc = 0u, it = kept;
                while (it){
                    int l = __ffs(it) - 1; it &= it - 1u;
                    acc |= sm[(b*32+l)*MASKW + lane];
                }
                sup |= acc;
            }
        }
        int ofs = 0;
        for (int bb=0; bb<v; bb+=32){
            int tp = bb + lane;
            int src = (tp < v) ? (tp>>5) : 0;
            unsigned wv = __shfl_sync(FULLM, sup, src);
            bool kp = (tp < v) && !((wv >> (tp&31)) & 1u);
            unsigned bal = __ballot_sync(FULLM, kp);
            int pos = ofs + __popc(bal & ((1u<<lane)-1u));
            if (kp && pos < DET){
                int n = g_vlist[g*NB+tp];
                unsigned kh = ~(__float_as_uint(g_psc[g*NB+tp]) | 0x80000000u);
                unsigned fidx = (unsigned)(cf*NB + n);
                g_gkeys[g*DET+pos] = (((unsigned long long)kh) << 32) | fidx;
            }
            ofs += __popc(bal);
            if (ofs >= DET) break;
        }
        if (lane == 0) g_kcnt[g] = ofs < DET ? ofs : DET;
    }
}

// ---------------- kernel 3: per-image top-100 via multiway-merge rank ----------------
__global__ void __launch_bounds__(512) k_topk(float* __restrict__ out, int out_size)
{
    __shared__ unsigned long long sk[NFG*DET];
    __shared__ unsigned long long stage[DET];
    __shared__ int soff[NFG+1];

    int b = blockIdx.x;
    int t = threadIdx.x;

    if (t == 0){
        int acc = 0;
        #pragma unroll
        for (int i=0;i<NFG;i++){ soff[i] = acc; acc += g_kcnt[b*NFG+i]; }
        soff[NFG] = acc;
    }
    if (t < DET) stage[t] = 0xFFFFFFFFFFFFFFFFull;   // real keys have MSB=0
    __syncthreads();
    int M = soff[NFG];
    int need = M < DET ? M : DET;

    #pragma unroll
    for (int gi=0; gi<NFG; gi++){
        int off = soff[gi];
        int cnt = soff[gi+1] - off;
        for (int p=t; p<cnt; p+=512) sk[off+p] = g_gkeys[(b*NFG+gi)*DET + p];
    }
    __syncthreads();

    // exact global rank: rank = local_idx + sum of lower_bounds in other lists
    for (int c = t; c < M; c += 512){
        int gi = 0;
        #pragma unroll
        for (int q=1;q<NFG;q++) gi += (soff[q] <= c);
        int j = c - soff[gi];
        if (j >= need) continue;
        unsigned long long k = sk[c];
        int rank = j;
        #pragma unroll 1
        for (int og = 0; og < NFG; og++){
            if (og == gi) continue;
            int lo = soff[og], hi = soff[og+1];
            while (lo < hi){
                int mid = (lo + hi) >> 1;
                if (sk[mid] < k) lo = mid + 1; else hi = mid;
            }
            rank += lo - soff[og];
            if (rank >= need) break;
        }
        if (rank < need) stage[rank] = k;    // ranks unique (keys unique)
    }
    __syncthreads();

    if (t < DET){
        unsigned long long key = stage[t];
        bool okd = (key != 0xFFFFFFFFFFFFFFFFull);
        float vals[6] = {0.f,0.f,0.f,0.f,0.f,0.f};
        float lab = 0.0f;
        if (okd){
            unsigned f  = (unsigned)(key & 0xFFFFFFFFull);
            unsigned ub = ~((unsigned)(key >> 32));
            float sc = __uint_as_float(ub ^ 0x80000000u);   // kept scores > 0
            int bi = b*NFG*NB + (int)f;
            #pragma unroll
            for (int kk=0;kk<5;kk++) vals[kk] = g_boxes[bi*5+kk];
            vals[5] = sc;
            lab = (float)((int)f / NB + 1);
        }
        int base = b*DET*6 + t*6;
        #pragma unroll
        for (int kk=0;kk<6;kk++) if (base+kk < out_size) out[base+kk] = vals[kk];
        int li = NIMG*DET*6 + b*DET + t;
        if (li < out_size) out[li] = lab;
    }
}

// ---------------- launcher ----------------
extern "C" void kernel_launch(void* const* d_in, const int* in_sizes, int n_in,
                              void* d_out, int out_size)
{
    const float* logits = (const float*)d_in[0];   // (768, 11)
    const float* reg    = (const float*)d_in[1];   // (768, 55)
    const float* rr     = (const float*)d_in[2];   // (768, 5)

    k_decpairs<<<NGRP*MASKW, THREADS>>>(logits, reg, rr);
    k_greedy  <<<NGRP, 256>>>();
    k_topk    <<<NIMG, 512>>>((float*)d_out, out_size);
}

// round 16
// speedup vs baseline: 1.8419x; 1.5074x over previous
#include <cuda_runtime.h>

// ---------------- problem constants ----------------
#define NB    384          // proposals per image
#define NC    11           // classes incl background
#define NFG   10           // foreground classes
#define NIMG  2            // images
#define NGRP  (NIMG*NFG)   // 20 NMS groups
#define MTOT  (NIMG*NB)    // 768 proposals
#define DET   100
#define MASKW 12           // ceil(384/32)
#define EPSF  1e-8f
#define SCORE_TH 0.05f
#define NMS_TH   0.5f
#define XFORM_CLIP 4.135166556742356f   // log(1000/16)
#define FULLM 0xFFFFFFFFu
#define SUBB  37           // pair-kernel blocks per group
#define QMAX  2048         // max pairs per block
#define CANDC 2048         // candidate buffer (top-k select)

// ---------------- device scratch (no allocs allowed) ----------------
__device__ float    g_boxes [NGRP*NB*5];
__device__ float    g_kept  [NGRP*NB];
__device__ int      g_vcnt  [NGRP];
__device__ int      g_vlist [NGRP*NB];
__device__ float    g_psc   [NGRP*NB];
__device__ float4   g_pcorn4[NGRP*NB*2];   // corners as 2x float4 (sorted order)
__device__ float4   g_pmeta [NGRP*NB];     // (cx, cy, area, rad)  (sorted order)
__device__ unsigned g_mask  [NGRP*NB*MASKW];

// ---------------- kernel 1: fused decode + softmax + sort + permute ----------------
__global__ void __launch_bounds__(512) k_decsort(const float* __restrict__ logits,
                                                 const float* __restrict__ reg,
                                                 const float* __restrict__ rr)
{
    __shared__ unsigned long long skeys[512];
    __shared__ float scorn[NB*8];
    __shared__ float4 smeta[NB];

    int g = blockIdx.x;
    int t = threadIdx.x;
    int b = g / NFG, cf = g % NFG, c = cf + 1;

    bool val = false;
    unsigned long long key;
    if (t < NB){
        int m = b*NB + t;
        float mx = -1e30f;
        float l[NC];
        #pragma unroll
        for (int k=0;k<NC;k++){ l[k] = __ldg(&logits[m*NC+k]); mx = fmaxf(mx, l[k]); }
        float s = 0.f;
        #pragma unroll
        for (int k=0;k<NC;k++) s += expf(l[k]-mx);
        float prob = expf(l[c]-mx)/s;

        float xc = __ldg(&rr[m*5+0]), yc = __ldg(&rr[m*5+1]);
        float w  = __ldg(&rr[m*5+2]), h  = __ldg(&rr[m*5+3]), a = __ldg(&rr[m*5+4]);

        const float* r = &reg[m*(NC*5) + c*5];
        float dx = __ldg(&r[0])/10.0f;
        float dy = __ldg(&r[1])/10.0f;
        float dw = fminf(__ldg(&r[2])/5.0f, XFORM_CLIP);
        float dh = fminf(__ldg(&r[3])/5.0f, XFORM_CLIP);
        float da = __ldg(&r[4]);

        float px = dx*w + xc;
        float py = dy*h + yc;
        float pw = expf(dw)*w;
        float ph = expf(dh)*h;
        float pa = da*(float)(180.0/3.14159265358979323846) + a;
        float x2 = pa + 180.0f;
        float rm = fmodf(x2, 360.0f);
        if (rm < 0.0f) rm += 360.0f;
        pa = rm - 180.0f;

        int o = g*NB + t;
        g_boxes[o*5+0] = px; g_boxes[o*5+1] = py;
        g_boxes[o*5+2] = pw; g_boxes[o*5+3] = ph; g_boxes[o*5+4] = pa;
        g_kept[o]      = -1.0f;                 // reset each graph replay

        smeta[t] = make_float4(px, py, pw*ph, 0.5f*sqrtf(pw*pw + ph*ph));

        float th = pa*(float)(3.14159265358979323846/180.0);
        float cs = cosf(th), sn = sinf(th);
        float hx = pw*0.5f, hy = ph*0.5f;
        float lx[4] = {-hx, hx, hx, -hx};
        float ly[4] = {-hy, -hy, hy, hy};
        #pragma unroll
        for (int k=0;k<4;k++){
            scorn[t*8+2*k]   = px + lx[k]*cs - ly[k]*sn;
            scorn[t*8+2*k+1] = py + lx[k]*sn + ly[k]*cs;
        }

        val = prob > SCORE_TH;
        float kf = val ? prob : __int_as_float(0xFF800000);
        unsigned ub = __float_as_uint(kf);
        ub = (ub & 0x80000000u) ? ~ub : (ub | 0x80000000u);
        key = (((unsigned long long)(~ub)) << 32) | (unsigned)t;
    } else {
        key = 0xFFFFFFFF00000000ull | (unsigned)t;
    }
    // zero this group's suppression mask (graph replays!)
    for (int w = t; w < NB*MASKW; w += 512) g_mask[g*NB*MASKW + w] = 0u;
    int vv = __syncthreads_count(val);
    if (t == 0) g_vcnt[g] = vv;

    // hybrid bitonic: shared for j>=32, shfl for j<32 (ascending == score desc)
    #pragma unroll
    for (int k=2;k<=512;k<<=1){
        #pragma unroll
        for (int j=k>>1;j>=32;j>>=1){
            skeys[t]=key; __syncthreads();
            unsigned long long o = skeys[t^j]; __syncthreads();
            bool up = ((t&k)==0), lower = ((t&j)==0);
            key = ((key<o)==(lower==up)) ? key : o;
        }
        int jmax = (k>>1) < 16 ? (k>>1) : 16;
        #pragma unroll
        for (int j=jmax;j>0;j>>=1){
            unsigned long long o = __shfl_xor_sync(FULLM, key, j);
            bool up = ((t&k)==0), lower = ((t&j)==0);
            key = ((key<o)==(lower==up)) ? key : o;
        }
    }

    // permute per-box data into sorted order (from shared)
    if (t < vv){
        int n = (int)(key & 0xFFFFFFFFull);
        unsigned ub = ~(unsigned)(key >> 32);
        unsigned bits = (ub & 0x80000000u) ? (ub ^ 0x80000000u) : ~ub;
        int q = g*NB + t;
        g_vlist[q] = n;
        g_psc[q]   = __uint_as_float(bits);
        const float* cp = &scorn[n*8];
        g_pcorn4[q*2+0] = make_float4(cp[0],cp[1],cp[2],cp[3]);
        g_pcorn4[q*2+1] = make_float4(cp[4],cp[5],cp[6],cp[7]);
        g_pmeta[q] = smeta[n];
    }
}

// ---------------- rotated-rect intersection: register-only, bitonic-32 network ----------------
__device__ __forceinline__ float crs(float ax,float ay,float bx,float by){
    return ax*by - ay*bx;
}

__device__ __forceinline__ float inter_area_reg(float4 ca0, float4 ca1,
                                                float4 cb0, float4 cb1)
{
    float ax[4] = {ca0.x, ca0.z, ca1.x, ca1.z};
    float ay[4] = {ca0.y, ca0.w, ca1.y, ca1.w};
    float bx4[4] = {cb0.x, cb0.z, cb1.x, cb1.z};
    float by4[4] = {cb0.y, cb0.w, cb1.y, cb1.w};
    float d1x[4],d1y[4],d2x[4],d2y[4];
    #pragma unroll
    for (int k=0;k<4;k++){
        d1x[k]=ax[(k+1)&3]-ax[k];  d1y[k]=ay[(k+1)&3]-ay[k];
        d2x[k]=bx4[(k+1)&3]-bx4[k]; d2y[k]=by4[(k+1)&3]-by4[k];
    }

    float px[24], py[24]; bool ok[24];
    #pragma unroll
    for (int i=0;i<4;i++){
        #pragma unroll
        for (int j=0;j<4;j++){
            float den  = crs(d1x[i],d1y[i],d2x[j],d2y[j]);
            float dfx  = bx4[j]-ax[i], dfy = by4[j]-ay[i];
            float dens = (fabsf(den) < EPSF) ? 1.0f : den;
            float t = crs(dfx,dfy,d2x[j],d2y[j]) / dens;
            float u = crs(dfx,dfy,d1x[i],d1y[i]) / dens;
            bool o = (fabsf(den) >= EPSF) && (t>=0.0f) && (t<=1.0f) && (u>=0.0f) && (u<=1.0f);
            px[4*i+j] = ax[i] + t*d1x[i];
            py[4*i+j] = ay[i] + t*d1y[i];
            ok[4*i+j] = o;
        }
    }
    #pragma unroll
    for (int p=0;p<4;p++){
        bool allpos=true, allneg=true;
        #pragma unroll
        for (int e=0;e<4;e++){
            float cr = crs(d2x[e],d2y[e], ax[p]-bx4[e], ay[p]-by4[e]);
            allpos = allpos && (cr >= -1e-6f);
            allneg = allneg && (cr <=  1e-6f);
        }
        ok[16+p] = allpos || allneg;
        px[16+p] = ax[p]; py[16+p] = ay[p];
    }
    #pragma unroll
    for (int p=0;p<4;p++){
        bool allpos=true, allneg=true;
        #pragma unroll
        for (int e=0;e<4;e++){
            float cr = crs(d1x[e],d1y[e], bx4[p]-ax[e], by4[p]-ay[e]);
            allpos = allpos && (cr >= -1e-6f);
            allneg = allneg && (cr <=  1e-6f);
        }
        ok[20+p] = allpos || allneg;
        px[20+p] = bx4[p]; py[20+p] = by4[p];
    }

    int nv = 0; float cx = 0.0f, cy = 0.0f;
    #pragma unroll
    for (int i=0;i<24;i++) if (ok[i]){ nv++; cx += px[i]; cy += py[i]; }
    if (nv < 3) return 0.0f;
    cx /= (float)nv;  cy /= (float)nv;

    // reference semantics: 24 points, invalid parked AT centroid with angle +0,
    // sorted by angle, shoelace over cyclic order. Ties occur only among
    // coordinate-identical centroid copies -> any order gives the same sum.
    unsigned kk[32];
    float sxp[32], syp[32];
    #pragma unroll
    for (int i=0;i<24;i++){
        bool o = ok[i];
        float x = o ? px[i] : cx;
        float y = o ? py[i] : cy;
        float a = o ? atan2f(y-cy, x-cx) : 0.0f;
        unsigned u = __float_as_uint(a);
        u = (u & 0x80000000u) ? ~u : (u | 0x80000000u);
        kk[i] = u; sxp[i] = x; syp[i] = y;
    }
    #pragma unroll
    for (int i=24;i<32;i++){ kk[i] = 0xFFFFFFFFu; sxp[i] = cx; syp[i] = cy; }

    #pragma unroll
    for (int k=2;k<=32;k<<=1){
        #pragma unroll
        for (int j=k>>1;j>0;j>>=1){
            #pragma unroll
            for (int ii=0;ii<32;ii++){
                int jj = ii ^ j;
                if (jj > ii){
                    bool up = ((ii & k) == 0);
                    bool sw = (kk[ii] > kk[jj]) == up;
                    unsigned ka=kk[ii], kb=kk[jj];
                    float xa=sxp[ii], xb=sxp[jj];
                    float ya=syp[ii], yb=syp[jj];
                    kk[ii]=sw?kb:ka;  kk[jj]=sw?ka:kb;
                    sxp[ii]=sw?xb:xa; sxp[jj]=sw?xa:xb;
                    syp[ii]=sw?yb:ya; syp[jj]=sw?ya:yb;
                }
            }
        }
    }
    float s = 0.0f;
    #pragma unroll
    for (int i=0;i<24;i++){
        int jn = (i+1) % 24;
        s += sxp[i]*syp[jn] - syp[i]*sxp[jn];
    }
    return 0.5f*fabsf(s);
}

// ---------------- kernel 2: prefilter -> queue -> full-warp clips ----------------
__global__ void __launch_bounds__(256) k_pairs()
{
    __shared__ int qcnt;
    __shared__ int queue[QMAX];

    int g   = blockIdx.x / SUBB;
    int sub = blockIdx.x % SUBB;
    int v = g_vcnt[g];
    int P = v*(v-1)/2;
    int base = g*NB;

    if (threadIdx.x == 0) qcnt = 0;
    __syncthreads();

    // phase 1: prefilters only; push survivors
    for (int p = sub*256 + threadIdx.x; p < P; p += SUBB*256){
        int j = (int)((1.0f + sqrtf(1.0f + 8.0f*(float)p))*0.5f);
        while (j*(j-1)/2 > p) j--;
        while ((j+1)*j/2 <= p) j++;
        int i = p - j*(j-1)/2;

        float4 mi = g_pmeta[base+i];
        float4 mj = g_pmeta[base+j];
        float aA = mi.z, aB = mj.z;
        float mn = fminf(aA,aB), sm = aA + aB;
        if (3.0f*mn <= sm*(1.0f - 1e-4f)) continue;      // IoU<=0.5 certain
        float dx = mi.x-mj.x, dy = mi.y-mj.y;
        float rr = mi.w+mj.w;
        if (dx*dx + dy*dy >= rr*rr) continue;            // disjoint
        int slot = atomicAdd(&qcnt, 1);
        if (slot < QMAX) queue[slot] = (i<<9) | j;
    }
    __syncthreads();
    int Q = qcnt < QMAX ? qcnt : QMAX;

    // phase 2: full warps do clips in lockstep (no divergence serialization)
    for (int q = threadIdx.x; q < Q; q += 256){
        int pk = queue[q];
        int i = pk >> 9, j = pk & 511;
        float4 ca0 = g_pcorn4[(base+i)*2+0], ca1 = g_pcorn4[(base+i)*2+1];
        float4 cb0 = g_pcorn4[(base+j)*2+0], cb1 = g_pcorn4[(base+j)*2+1];
        float inter = inter_area_reg(ca0, ca1, cb0, cb1);
        float aA = g_pmeta[base+i].z, aB = g_pmeta[base+j].z;
        float iou = inter / (aA + aB - inter + EPSF);
        if (iou > NMS_TH)
            atomicOr(&g_mask[(base+i)*MASKW + (j>>5)], 1u << (j&31));
    }
}

// ---------------- kernel 3: greedy — block-wise register-serial chain -> g_kept ----------------
__global__ void __launch_bounds__(256) k_greedy()
{
    __shared__ unsigned sm[NB*MASKW];
    __shared__ unsigned sblk[MASKW];
    int g = blockIdx.x;
    int t = threadIdx.x;
    int v = g_vcnt[g];

    for (int w = t; w < v*MASKW; w += 256) sm[w] = g_mask[g*NB*MASKW + w];
    if (t < MASKW) sblk[t] = 0u;
    __syncthreads();

    int B = (v + 31) & ~31;
    for (int r0 = t; r0 < B; r0 += 256){
        bool any = false;
        if (r0 < v){
            unsigned o = 0u;
            #pragma unroll
            for (int w=0;w<MASKW;w++) o |= sm[r0*MASKW+w];
            any = (o != 0u);
        }
        unsigned bal = __ballot_sync(FULLM, any);
        if ((t & 31) == 0) sblk[r0 >> 5] = bal;
    }
    __syncthreads();

    if (t < 32){
        int lane = t;
        unsigned sup = 0u;                       // lane b owns sup word b
        int nblk = (v + 31) >> 5;
        for (int b=0; b<nblk; b++){
            unsigned sb = sblk[b];
            if (sb == 0u) continue;              // no suppressors in block
            unsigned s = __shfl_sync(FULLM, sup, b);
            if (lane == 0){
                unsigned it = sb;                // ascending row order
                while (it){
                    int l = __ffs(it) - 1; it &= it - 1u;
                    if (!((s >> l) & 1u)) s |= sm[(b*32+l)*MASKW + b];
                }
            }
            s = __shfl_sync(FULLM, s, 0);
            unsigned kept = (~s) & sb;           // kept suppressor rows
            if (lane < MASKW){
                unsigned acc = 0u, it = kept;
                while (it){
                    int l = __ffs(it) - 1; it &= it - 1u;
                    acc |= sm[(b*32+l)*MASKW + lane];
                }
                sup |= acc;
            }
        }
        for (int base=0; base<v; base+=32){
            int tp = base + lane;
            int src = (tp < v) ? (tp>>5) : 0;
            unsigned wv = __shfl_sync(FULLM, sup, src);
            if (tp < v && !((wv >> (tp&31)) & 1u)){
                int n = g_vlist[g*NB+tp];
                g_kept[g*NB+n] = g_psc[g*NB+tp];
            }
        }
    }
}

// ---------------- kernel 4: per-image top-100 via histogram rank-select ----------------
__global__ void __launch_bounds__(512) k_topk(float* __restrict__ out, int out_size)
{
    __shared__ int hist[2048];
    __shared__ unsigned long long cand[CANDC];
    __shared__ int ccnt;
    __shared__ int s_thresh;
    __shared__ int warpsum[16];

    int b = blockIdx.x;
    int t = threadIdx.x;
    int lane = t & 31, wid = t >> 5;

    for (int i=t;i<2048;i+=512) hist[i]=0;
    if (t==0){ ccnt=0; s_thresh=-1; }
    __syncthreads();

    // pass 1: histogram over top-11 bits of (~ub) key
    for (int f=t; f<NFG*NB; f+=512){
        float sc = g_kept[b*NFG*NB + f];
        if (sc > 0.0f){
            unsigned kh = ~(__float_as_uint(sc) | 0x80000000u);
            atomicAdd(&hist[kh>>21], 1);
        }
    }
    __syncthreads();

    // prefix scan over 2048 bins, 4 bins/thread
    int h0=hist[t*4], h1=hist[t*4+1], h2=hist[t*4+2], h3=hist[t*4+3];
    int local = h0+h1+h2+h3;
    int x = local;
    #pragma unroll
    for (int o=1;o<32;o<<=1){ int y=__shfl_up_sync(FULLM,x,o); if (lane>=o) x+=y; }
    if (lane==31) warpsum[wid]=x;
    __syncthreads();
    if (wid==0){
        int y = (lane<16)? warpsum[lane] : 0;
        #pragma unroll
        for (int o=1;o<16;o<<=1){ int z=__shfl_up_sync(FULLM,y,o); if (lane>=o) y+=z; }
        if (lane<16) warpsum[lane]=y;
    }
    __syncthreads();
    int totalK = warpsum[15];
    int need = totalK < DET ? totalK : DET;
    int incl = x + ((wid>0)? warpsum[wid-1] : 0);
    int excl = incl - local;
    if (need > 0){
        int c0=excl+h0, c1=c0+h1, c2=c1+h2, c3=c2+h3;
        int tb=-1;
        if (excl<need && c0>=need) tb=t*4;
        else if (c0<need && c1>=need) tb=t*4+1;
        else if (c1<need && c2>=need) tb=t*4+2;
        else if (c2<need && c3>=need) tb=t*4+3;
        if (tb>=0) s_thresh = tb;                 // exactly one writer
    }
    __syncthreads();
    int T = s_thresh;

    // pass 2: compact candidates (bins <= T); count <= 99 + |bin T|
    if (T >= 0){
        for (int f=t; f<NFG*NB; f+=512){
            float sc = g_kept[b*NFG*NB + f];
            if (sc > 0.0f){
                unsigned kh = ~(__float_as_uint(sc) | 0x80000000u);
                if ((int)(kh>>21) <= T){
                    int p = atomicAdd(&ccnt, 1);
                    if (p < CANDC)
                        cand[p] = (((unsigned long long)kh) << 32) | (unsigned)f;
                }
            }
        }
    }
    __syncthreads();
    int Kc = ccnt < CANDC ? ccnt : CANDC;
    int P = 128;
    while (P < Kc) P <<= 1;                        // P <= CANDC
    for (int f = Kc + t; f < P; f += 512) cand[f] = 0xFFFFFFFFFFFFFFFFull;
    __syncthreads();

    for (int k=2;k<=P;k<<=1)
        for (int j=k>>1;j>0;j>>=1){
            for (int p=t;p<P;p+=512){
                int ixj = p ^ j;
                if (ixj > p){
                    unsigned long long A = cand[p], Bv = cand[ixj];
                    if ((A > Bv) == ((p & k) == 0)){ cand[p] = Bv; cand[ixj] = A; }
                }
            }
            __syncthreads();
        }

    if (t < DET){
        unsigned long long key = (t < P) ? cand[t] : 0xFFFFFFFFFFFFFFFFull;
        unsigned f  = (unsigned)(key & 0xFFFFFFFFull);
        unsigned ub = ~((unsigned)(key >> 32));
        unsigned bits = (ub & 0x80000000u) ? (ub ^ 0x80000000u) : ~ub;
        float sc = __uint_as_float(bits);
        bool okd = (t < Kc) && (sc > 0.0f);

        float vals[6] = {0.f,0.f,0.f,0.f,0.f,0.f};
        float lab = 0.0f;
        if (okd){
            int bi = b*NFG*NB + (int)f;
            #pragma unroll
            for (int kk=0;kk<5;kk++) vals[kk] = g_boxes[bi*5+kk];
            vals[5] = sc;
            lab = (float)((int)f / NB + 1);
        }
        int base = b*DET*6 + t*6;
        #pragma unroll
        for (int kk=0;kk<6;kk++) if (base+kk < out_size) out[base+kk] = vals[kk];
        int li = NIMG*DET*6 + b*DET + t;
        if (li < out_size) out[li] = lab;
    }
}

// ---------------- launcher ----------------
extern "C" void kernel_launch(void* const* d_in, const int* in_sizes, int n_in,
                              void* d_out, int out_size)
{
    const float* logits = (const float*)d_in[0];   // (768, 11)
    const float* reg    = (const float*)d_in[1];   // (768, 55)
    const float* rr     = (const float*)d_in[2];   // (768, 5)

    k_decsort<<<NGRP, 512>>>(logits, reg, rr);
    k_pairs  <<<NGRP*SUBB, 256>>>();
    k_greedy <<<NGRP, 256>>>();
    k_topk   <<<NIMG, 512>>>((float*)d_out, out_size);
}